// round 1
// baseline (speedup 1.0000x reference)
#include <cuda_runtime.h>
#include <cuda_bf16.h>

#define IMAGE_TOKEN_ID 31999
#define BB 4
#define LL 1024
#define DD 2048
#define NUM_VIS 576
#define NEW_LEN (LL - 1 + NUM_VIS)   // 1599
#define D4 (DD / 4)                  // 512 float4 per row

__device__ int g_img_pos[BB];

// Pre-pass: find the (single) image-token position per row.
__global__ void find_img_pos_kernel(const int* __restrict__ ids) {
    int b = blockIdx.x;
    for (int i = threadIdx.x; i < LL; i += blockDim.x) {
        if (ids[b * LL + i] == IMAGE_TOKEN_ID) {
            g_img_pos[b] = i;   // exactly one per row -> single write
        }
    }
}

// One CTA per output row (b, j); 256 threads copy 512 float4.
__global__ void __launch_bounds__(256) merge_kernel(
    const int*    __restrict__ ids,
    const float4* __restrict__ vis,    // [B, NUM_VIS, D/4]
    const float4* __restrict__ embed,  // [32768, D/4]
    float4*       __restrict__ out)    // [B, NEW_LEN, D/4]
{
    int row = blockIdx.x;                 // 0 .. B*NEW_LEN-1
    int b = row / NEW_LEN;
    int j = row - b * NEW_LEN;
    int p = g_img_pos[b];

    const float4* src = nullptr;
    bool write_zero = false;

    if (j >= p && j < p + NUM_VIS) {
        // visual block
        src = vis + ((size_t)b * NUM_VIS + (j - p)) * D4;
    } else if (j == 0 && p != 0) {
        // reference's duplicate-scatter: image row's dummy zero-write to slot 0
        // lands after text position 0's write (XLA CPU in-order scatter).
        write_zero = true;
    } else {
        int i = (j < p) ? j : (j - NUM_VIS + 1);
        int tok = ids[b * LL + i];
        src = embed + (size_t)tok * D4;
    }

    float4* dst = out + (size_t)row * D4;
    int t = threadIdx.x;
    if (write_zero) {
        float4 z = make_float4(0.f, 0.f, 0.f, 0.f);
        dst[t]       = z;
        dst[t + 256] = z;
    } else {
        dst[t]       = src[t];
        dst[t + 256] = src[t + 256];
    }
}

// Tail: position_ids = broadcast arange(NEW_LEN), written as output dtype (fp32).
__global__ void pos_ids_kernel(float* __restrict__ tail, int n) {
    int i = blockIdx.x * blockDim.x + threadIdx.x;
    if (i < n) {
        tail[i] = (float)(i % NEW_LEN);
    }
}

extern "C" void kernel_launch(void* const* d_in, const int* in_sizes, int n_in,
                              void* d_out, int out_size) {
    const int*    ids   = (const int*)d_in[0];            // [B, L] int32
    const float4* vis   = (const float4*)d_in[1];         // [B, NUM_VIS, D]
    const float4* embed = (const float4*)d_in[2];         // [32768, D]
    float* out = (float*)d_out;

    find_img_pos_kernel<<<BB, 256>>>(ids);
    merge_kernel<<<BB * NEW_LEN, 256>>>(ids, vis, embed, (float4*)out);

    const int merged_elems = BB * NEW_LEN * DD;           // 13,099,008
    int tail_n = out_size - merged_elems;
    if (tail_n > 0) {
        pos_ids_kernel<<<(tail_n + 255) / 256, 256>>>(out + merged_elems, tail_n);
    }
}

// round 2
// speedup vs baseline: 1.1083x; 1.1083x over previous
#include <cuda_runtime.h>
#include <cuda_bf16.h>

#define IMAGE_TOKEN_ID 31999
#define BB 4
#define LL 1024
#define DD 2048
#define NUM_VIS 576
#define NEW_LEN (LL - 1 + NUM_VIS)   // 1599
#define D4 (DD / 4)                  // 512 float4 per row
#define MERGED_ROWS (BB * NEW_LEN)   // 6396
#define MERGED_ELEMS (MERGED_ROWS * DD)

__device__ int g_img_pos[BB];

// Pre-pass: one load per thread across all B*L ids -> single memory round-trip.
__global__ void __launch_bounds__(256) find_img_pos_kernel(const int* __restrict__ ids) {
    int idx = blockIdx.x * 256 + threadIdx.x;   // 0 .. B*L-1 (grid sized exactly)
    if (ids[idx] == IMAGE_TOKEN_ID) {
        g_img_pos[idx >> 10] = idx & (LL - 1);  // exactly one match per row
    }
}

// One CTA per output row (b, j); 256 threads copy 512 float4.
// Trailing blocks (blockIdx >= MERGED_ROWS) write the position_ids tail.
__global__ void __launch_bounds__(256) merge_kernel(
    const int*    __restrict__ ids,
    const float4* __restrict__ vis,    // [B, NUM_VIS, D/4]
    const float4* __restrict__ embed,  // [32768, D/4]
    float4*       __restrict__ out,    // [B, NEW_LEN, D/4]
    int tail_n)                        // # fp32 elements of position_ids tail
{
    int row = blockIdx.x;

    if (row >= MERGED_ROWS) {
        // position_ids tail: broadcast arange(NEW_LEN), as output dtype (fp32)
        int i = (row - MERGED_ROWS) * 256 + threadIdx.x;
        if (i < tail_n) {
            float* tail = (float*)out + (size_t)MERGED_ELEMS;
            tail[i] = (float)(i % NEW_LEN);
        }
        return;
    }

    int b = row / NEW_LEN;
    int j = row - b * NEW_LEN;
    int p = g_img_pos[b];

    const float4* src = nullptr;
    bool write_zero = false;

    if (j >= p && j < p + NUM_VIS) {
        // visual block
        src = vis + ((size_t)b * NUM_VIS + (j - p)) * D4;
    } else if (j == 0 && p != 0) {
        // reference's duplicate-scatter: image row's dummy zero-write to slot 0
        // lands after text position 0's write (XLA in-order scatter).
        write_zero = true;
    } else {
        int i = (j < p) ? j : (j - NUM_VIS + 1);
        int tok = ids[b * LL + i];
        src = embed + (size_t)tok * D4;
    }

    float4* dst = out + (size_t)row * D4;
    int t = threadIdx.x;
    if (write_zero) {
        float4 z = make_float4(0.f, 0.f, 0.f, 0.f);
        dst[t]       = z;
        dst[t + 256] = z;
    } else {
        float4 a0 = src[t];
        float4 a1 = src[t + 256];
        dst[t]       = a0;
        dst[t + 256] = a1;
    }
}

extern "C" void kernel_launch(void* const* d_in, const int* in_sizes, int n_in,
                              void* d_out, int out_size) {
    const int*    ids   = (const int*)d_in[0];            // [B, L] int32
    const float4* vis   = (const float4*)d_in[1];         // [B, NUM_VIS, D]
    const float4* embed = (const float4*)d_in[2];         // [32768, D]

    find_img_pos_kernel<<<(BB * LL) / 256, 256>>>(ids);

    int tail_n = out_size - MERGED_ELEMS;
    if (tail_n < 0) tail_n = 0;
    int tail_blocks = (tail_n + 255) / 256;
    merge_kernel<<<MERGED_ROWS + tail_blocks, 256>>>(
        ids, vis, embed, (float4*)d_out, tail_n);
}

// round 3
// speedup vs baseline: 1.2429x; 1.1214x over previous
#include <cuda_runtime.h>
#include <cuda_bf16.h>

#define IMAGE_TOKEN_ID 31999
#define BB 4
#define LL 1024
#define DD 2048
#define NUM_VIS 576
#define NEW_LEN (LL - 1 + NUM_VIS)   // 1599
#define D4 (DD / 4)                  // 512 float4 per row
#define MERGED_ROWS (BB * NEW_LEN)   // 6396
#define MERGED_ELEMS (MERGED_ROWS * DD)

// Single fused kernel. One CTA per output row (b, j); 256 threads copy 512
// float4. Each CTA finds its own row's image-token position by scanning the
// (L2-resident, 16 KB) ids array — no pre-pass kernel, no launch boundary.
// Trailing blocks write the position_ids tail.
__global__ void __launch_bounds__(256) merge_kernel(
    const int*    __restrict__ ids,    // [B, L]
    const float4* __restrict__ vis,    // [B, NUM_VIS, D/4]
    const float4* __restrict__ embed,  // [32768, D/4]
    float4*       __restrict__ out,    // [B, NEW_LEN, D/4] (+ tail)
    int tail_n)                        // # fp32 elements of position_ids tail
{
    int row = blockIdx.x;

    if (row >= MERGED_ROWS) {
        // position_ids tail: broadcast arange(NEW_LEN), as output dtype (fp32)
        int i = (row - MERGED_ROWS) * 256 + threadIdx.x;
        if (i < tail_n) {
            float* tail = (float*)out + (size_t)MERGED_ELEMS;
            tail[i] = (float)(i % NEW_LEN);
        }
        return;
    }

    int b = row / NEW_LEN;
    int j = row - b * NEW_LEN;
    int t = threadIdx.x;

    // ---- find this row's image-token position (exactly one per row) ----
    __shared__ int s_p;
    if (t == 0) s_p = 0;
    __syncthreads();
    const int* row_ids = ids + b * LL;
    #pragma unroll
    for (int k = 0; k < 4; k++) {
        int pos = t + k * 256;
        if (row_ids[pos] == IMAGE_TOKEN_ID) {
            atomicMax(&s_p, pos);   // single match; init 0 covers pos==0 case
        }
    }
    __syncthreads();
    int p = s_p;

    // ---- route this output row ----
    const float4* src = nullptr;
    bool write_zero = false;

    if (j >= p && j < p + NUM_VIS) {
        src = vis + ((size_t)b * NUM_VIS + (j - p)) * D4;
    } else if (j == 0 && p != 0) {
        // reference's duplicate-scatter: image row's dummy zero-write to slot 0
        // lands after text position 0's write (XLA in-order scatter).
        write_zero = true;
    } else {
        int i = (j < p) ? j : (j - NUM_VIS + 1);
        int tok = row_ids[i];
        src = embed + (size_t)tok * D4;
    }

    float4* dst = out + (size_t)row * D4;
    if (write_zero) {
        float4 z = make_float4(0.f, 0.f, 0.f, 0.f);
        __stcs(dst + t,       z);
        __stcs(dst + t + 256, z);
    } else {
        float4 a0 = __ldcs(src + t);
        float4 a1 = __ldcs(src + t + 256);
        __stcs(dst + t,       a0);
        __stcs(dst + t + 256, a1);
    }
}

extern "C" void kernel_launch(void* const* d_in, const int* in_sizes, int n_in,
                              void* d_out, int out_size) {
    const int*    ids   = (const int*)d_in[0];            // [B, L] int32
    const float4* vis   = (const float4*)d_in[1];         // [B, NUM_VIS, D]
    const float4* embed = (const float4*)d_in[2];         // [32768, D]

    int tail_n = out_size - MERGED_ELEMS;
    if (tail_n < 0) tail_n = 0;
    int tail_blocks = (tail_n + 255) / 256;

    merge_kernel<<<MERGED_ROWS + tail_blocks, 256>>>(
        ids, vis, embed, (float4*)d_out, tail_n);
}